// round 2
// baseline (speedup 1.0000x reference)
#include <cuda_runtime.h>
#include <math.h>
#include <stdint.h>

// Problem constants
#define BB   8
#define LL   1024
#define SSZ  1024
#define HHN  8
#define DDIM 64
#define NQV  4
#define BHN  (BB*HHN)

#define CTX_ELEMS (BB*LL*HHN*DDIM)          // context first in output
#define PI_F 3.14159274101257324f

// Scratch statevectors (packed for f32x2 FMA)
// Q: [bh][l][k(16)][4] = {qr, qi, qi, -qr}
// K: [bh][k(16)][s][4] = {kr, kr, ki, ki}
__device__ float g_qsv[(size_t)BHN * LL * 64];
__device__ float g_ksv[(size_t)BHN * SSZ * 64];

typedef unsigned long long u64;

__device__ __forceinline__ u64 pk2(float x, float y) {
    u64 r; asm("mov.b64 %0, {%1, %2};" : "=l"(r) : "f"(x), "f"(y)); return r;
}
__device__ __forceinline__ void ffma2(u64& d, u64 a, u64 b) {
    asm("fma.rn.f32x2 %0, %1, %2, %0;" : "+l"(d) : "l"(a), "l"(b));
}
__device__ __forceinline__ float2 upk2(u64 v) {
    float2 r; asm("mov.b64 {%0, %1}, %2;" : "=f"(r.x), "=f"(r.y) : "l"(v)); return r;
}
__device__ __forceinline__ void cpa16(void* smem_dst, const void* gsrc) {
    uint32_t s = (uint32_t)__cvta_generic_to_shared(smem_dst);
    asm volatile("cp.async.cg.shared.global [%0], [%1], 16;" :: "r"(s), "l"(gsrc));
}
__device__ __forceinline__ void cpa_wait() {
    asm volatile("cp.async.commit_group;\ncp.async.wait_group 0;" ::: "memory");
}

// ======================================================================
// Encode kernel (unchanged from R1): angles -> packed statevector.
// ======================================================================
__global__ void __launch_bounds__(256) encode_kernel(
    const float* __restrict__ x, const float* __restrict__ w,
    const float* __restrict__ bias, int isK)
{
    __shared__ float sw[NQV * DDIM];
    __shared__ float sb[NQV];
    int tid = threadIdx.x;
    if (tid < NQV * DDIM) sw[tid] = w[tid];
    if (tid < NQV) sb[tid] = bias[tid];
    __syncthreads();

    int n  = blockIdx.x * blockDim.x + tid;
    int bh = n >> 10;
    int loc = n & 1023;
    int b = bh >> 3, h = bh & 7;

    const float* xr = x + (size_t)((b * 1024 + loc) * HHN + h) * DDIM;

    float th[NQV];
#pragma unroll
    for (int j = 0; j < NQV; j++) th[j] = sb[j];
#pragma unroll 4
    for (int d = 0; d < DDIM; d += 4) {
        float4 xv = *(const float4*)(xr + d);
#pragma unroll
        for (int j = 0; j < NQV; j++) {
            th[j] += xv.x * sw[j * DDIM + d]     + xv.y * sw[j * DDIM + d + 1]
                   + xv.z * sw[j * DDIM + d + 2] + xv.w * sw[j * DDIM + d + 3];
        }
    }
#pragma unroll
    for (int j = 0; j < NQV; j++) th[j] = tanhf(th[j]) * PI_F;

    float bt[3];
#pragma unroll
    for (int p = 0; p < 3; p++) bt[p] = th[p] * th[p + 1];

    float co[16], si[16];
#pragma unroll
    for (int d = 0; d < 16; d++) {
        float a = 0.f;
        a += ((d >> 3) & 1) ? -th[0] : th[0];
        a += ((d >> 2) & 1) ? -th[1] : th[1];
        a += ((d >> 1) & 1) ? -th[2] : th[2];
        a += ( d       & 1) ? -th[3] : th[3];
        a += (((d >> 3) ^ (d >> 2)) & 1) ? -bt[0] : bt[0];
        a += (((d >> 2) ^ (d >> 1)) & 1) ? -bt[1] : bt[1];
        a += (((d >> 1) ^  d      ) & 1) ? -bt[2] : bt[2];
        sincosf(-0.5f * a, &si[d], &co[d]);
    }

    float re[16], im[16];
#pragma unroll
    for (int d = 0; d < 16; d++) { re[d] = co[d]; im[d] = si[d]; }
#pragma unroll
    for (int hs = 1; hs < 16; hs <<= 1) {
#pragma unroll
        for (int i = 0; i < 16; i++) {
            if ((i & hs) == 0) {
                int j2 = i | hs;
                float ar = re[i], ai = im[i], br = re[j2], bi = im[j2];
                re[i] = ar + br;  im[i] = ai + bi;
                re[j2] = ar - br; im[j2] = ai - bi;
            }
        }
    }

    if (!isK) {
        float4* outq = (float4*)g_qsv + (size_t)n * 16;
#pragma unroll
        for (int d = 0; d < 16; d++) {
            float tr = re[d] * 0.0625f, ti = im[d] * 0.0625f;
            float vr = tr * co[d] - ti * si[d];
            float vi = tr * si[d] + ti * co[d];
            outq[d] = make_float4(vr, vi, vi, -vr);
        }
    } else {
        float4* outk = (float4*)g_ksv;
#pragma unroll
        for (int d = 0; d < 16; d++) {
            float tr = re[d] * 0.0625f, ti = im[d] * 0.0625f;
            float vr = tr * co[d] - ti * si[d];
            float vi = tr * si[d] + ti * co[d];
            outk[(size_t)(bh * 16 + d) * 1024 + loc] = make_float4(vr, vr, vi, vi);
        }
    }
}

// ======================================================================
// Main fused kernel
// ======================================================================
#define TL 32
#define SCROW 1028
#define CS 256
#define OFF_Q  (TL*SCROW)            // floats: 32896
#define OFF_K  (OFF_Q + TL*64)       // floats: 34944
#define SMEM_BYTES (OFF_K*4 + 81920) // 221,696 B (V stage stride-20 layout)

__global__ void __launch_bounds__(256, 1) attn_main(
    const float* __restrict__ values,   // [B,S,H,D]
    float* __restrict__ out)            // [context | weights]
{
    extern __shared__ float smem[];
    float* sc  = smem;                  // [32][1028] raw scores
    float* qsm = smem + OFF_Q;          // [32][64] packed q tile
    float* ksm = smem + OFF_K;          // K chunk / padded V chunk / reduce buf
    __shared__ float sinv[TL];

    const int bh = blockIdx.y;
    const int l0 = blockIdx.x * TL;
    const int b = bh >> 3, h = bh & 7;
    const int tid = threadIdx.x;
    const int w = tid >> 5, lane = tid & 31;
    const int lgrp = w & 3, ssub = w >> 2;

    // stage Q tile (async; wait folded into first K chunk wait)
    {
        const float4* qg = (const float4*)g_qsv + (size_t)(bh * 1024 + l0) * 16;
        for (int i = tid; i < TL * 16; i += 256) cpa16((float4*)qsm + i, qg + i);
    }

    // ---- phase A: scores (nl=8 x ns=4 register tile, chunk 256) ----
    const float4* kg = (const float4*)g_ksv + (size_t)bh * 16 * 1024;
    for (int c = 0; c < 4; c++) {
        const int s0 = c * CS;
        __syncthreads();
#pragma unroll
        for (int j = 0; j < 16; j++) {
            int i = tid + j * 256;
            int kk = i >> 8, s = i & 255;
            cpa16((float4*)ksm + i, kg + kk * 1024 + s0 + s);
        }
        cpa_wait();
        __syncthreads();

        u64 acc[8][4];
#pragma unroll
        for (int il = 0; il < 8; il++)
#pragma unroll
            for (int is = 0; is < 4; is++) acc[il][is] = 0ull;

        const ulonglong2* q2 = (const ulonglong2*)qsm;
        const ulonglong2* k2 = (const ulonglong2*)ksm;
#pragma unroll
        for (int k = 0; k < 16; k++) {
            ulonglong2 kv[4];
#pragma unroll
            for (int is = 0; is < 4; is++)
                kv[is] = k2[k * 256 + ssub * 128 + is * 32 + lane];
#pragma unroll
            for (int il = 0; il < 8; il++) {
                ulonglong2 qv = q2[(lgrp * 8 + il) * 16 + k];
#pragma unroll
                for (int is = 0; is < 4; is++) {
                    ffma2(acc[il][is], qv.x, kv[is].x);
                    ffma2(acc[il][is], qv.y, kv[is].y);
                }
            }
        }
#pragma unroll
        for (int il = 0; il < 8; il++)
#pragma unroll
            for (int is = 0; is < 4; is++) {
                float2 f = upk2(acc[il][is]);
                sc[(lgrp * 8 + il) * SCROW + s0 + ssub * 128 + is * 32 + lane]
                    = f.x * f.x + f.y * f.y;
            }
    }
    __syncthreads();

    // ---- rowsums ----
    {
#pragma unroll
        for (int r = 0; r < 4; r++) {
            int l = w * 4 + r;
            const float4* row = (const float4*)&sc[l * SCROW];
            float4 a4 = make_float4(0.f, 0.f, 0.f, 0.f);
            for (int i = lane; i < 256; i += 32) {
                float4 v = row[i];
                a4.x += v.x; a4.y += v.y; a4.z += v.z; a4.w += v.w;
            }
            float s = (a4.x + a4.y) + (a4.z + a4.w);
#pragma unroll
            for (int o = 16; o; o >>= 1) s += __shfl_xor_sync(0xFFFFFFFFu, s, o);
            if (lane == 0) sinv[l] = 1.0f / (s + 1e-6f);
        }
    }
    __syncthreads();

    // ---- phase B: weights out (STGs drain during phase C) ----
    {
        float4* wout = (float4*)(out + (size_t)CTX_ELEMS + ((size_t)bh * 1024 + l0) * 1024);
        for (int i = tid; i < TL * 256; i += 256) {
            int l = i >> 8, s4 = i & 255;
            float4 v = ((const float4*)&sc[l * SCROW])[s4];
            float iv = sinv[l];
            v.x *= iv; v.y *= iv; v.z *= iv; v.w *= iv;
            wout[(size_t)l * 256 + s4] = v;
        }
    }

    // ---- phase C: context. thread = (1 l-row, 8 d-pairs). warps: 4 lgrp x 2 shalf ----
    const int l_in = lane >> 2, dpg = lane & 3;
    const int lC = lgrp * 8 + l_in;
    u64 cacc[8];
#pragma unroll
    for (int m = 0; m < 8; m++) cacc[m] = 0ull;

    const float4* vg = (const float4*)values;
    for (int c = 0; c < 4; c++) {
        const int s0 = c * CS;
        __syncthreads();
#pragma unroll
        for (int j = 0; j < 16; j++) {
            int i = tid + j * 256;
            int s = i >> 4, dq = i & 15;
            int dst = s * 20 + (dq >> 2) * 5 + (dq & 3);   // padded: conflict-free reads
            cpa16((float4*)ksm + dst,
                  vg + ((size_t)((b * 1024 + s0 + s) * HHN + h)) * 16 + dq);
        }
        cpa_wait();
        __syncthreads();

        const ulonglong2* vp2 = (const ulonglong2*)ksm;
        const float* scrow = &sc[lC * SCROW + s0];
        const int sbeg = ssub * 128;
#pragma unroll 2
        for (int sb = 0; sb < 128; sb += 4) {
            float4 w4 = *(const float4*)&scrow[sbeg + sb];
#pragma unroll
            for (int js = 0; js < 4; js++) {
                float wv = (js == 0) ? w4.x : (js == 1) ? w4.y : (js == 2) ? w4.z : w4.w;
                u64 ws = pk2(wv, wv);
#pragma unroll
                for (int m = 0; m < 4; m++) {
                    ulonglong2 vv = vp2[(sbeg + sb + js) * 20 + dpg * 5 + m];
                    ffma2(cacc[m * 2],     ws, vv.x);
                    ffma2(cacc[m * 2 + 1], ws, vv.y);
                }
            }
        }
    }
    __syncthreads();

    // cross-s-half reduction via smem, scale by 1/rowsum, store context
    u64* red = (u64*)ksm;
    const int ridx = (lC * 4 + dpg) * 8;
    if (ssub == 0) {
#pragma unroll
        for (int m = 0; m < 8; m++) red[ridx + m] = cacc[m];
    }
    __syncthreads();
    if (ssub == 1) {
        float iv = sinv[lC];
        float2* co = (float2*)out + ((size_t)((b * 1024 + l0 + lC) * HHN + h)) * 32 + dpg * 8;
#pragma unroll
        for (int m = 0; m < 8; m++) {
            float2 p = upk2(red[ridx + m]);
            float2 o = upk2(cacc[m]);
            co[m] = make_float2((p.x + o.x) * iv, (p.y + o.y) * iv);
        }
    }
}

// ======================================================================
extern "C" void kernel_launch(void* const* d_in, const int* in_sizes, int n_in,
                              void* d_out, int out_size)
{
    (void)in_sizes; (void)n_in; (void)out_size;
    const float* q  = (const float*)d_in[0];
    const float* k  = (const float*)d_in[1];
    const float* v  = (const float*)d_in[2];
    const float* wq = (const float*)d_in[3];
    const float* bq = (const float*)d_in[4];
    const float* wk = (const float*)d_in[5];
    const float* bk = (const float*)d_in[6];
    float* out = (float*)d_out;

    cudaFuncSetAttribute(attn_main, cudaFuncAttributeMaxDynamicSharedMemorySize, SMEM_BYTES);

    encode_kernel<<<256, 256>>>(q, wq, bq, 0);
    encode_kernel<<<256, 256>>>(k, wk, bk, 1);
    attn_main<<<dim3(LL / TL, BHN), 256, SMEM_BYTES>>>(v, out);
}

// round 3
// speedup vs baseline: 1.7875x; 1.7875x over previous
#include <cuda_runtime.h>
#include <math.h>
#include <stdint.h>

#define BB   8
#define LL   1024
#define HHN  8
#define DDIM 64
#define NQV  4
#define BHN  (BB*HHN)
#define CTX_ELEMS (BB*LL*HHN*DDIM)
#define PI_F 3.14159274101257324f

// tf32-split operand buffers
// g_qA: [bh][row=2l+kind][64] rows: [a_hi(32) | a_lo(32)], a=(Re0..15,Im0..15), b=(Im, -Re)
__device__ float g_qA[(size_t)BHN * 2048 * 64];
// g_kB: [bh][s][64] = [k_hi(32) | k_lo(32)], k = (Re0..15, Im0..15)
__device__ float g_kB[(size_t)BHN * 1024 * 64];
// g_vS: [bh][s][128] = [v_hi(64) | v_lo(64)]
__device__ float g_vS[(size_t)BHN * 1024 * 128];
__device__ float g_rsum[BHN * 1024];

// ---------------- helpers ----------------
__device__ __forceinline__ void tsplit(float x, float& hi, float& lo) {
    uint32_t hb; asm("cvt.rna.tf32.f32 %0, %1;" : "=r"(hb) : "f"(x));
    hi = __uint_as_float(hb);
    float l = x - hi;
    uint32_t lb; asm("cvt.rna.tf32.f32 %0, %1;" : "=r"(lb) : "f"(l));
    lo = __uint_as_float(lb);
}
__device__ __forceinline__ void mma_tf32(float4& c, const uint32_t a[4],
                                         uint32_t b0, uint32_t b1) {
    asm("mma.sync.aligned.m16n8k8.row.col.f32.tf32.tf32.f32 "
        "{%0,%1,%2,%3},{%4,%5,%6,%7},{%8,%9},{%0,%1,%2,%3};"
        : "+f"(c.x), "+f"(c.y), "+f"(c.z), "+f"(c.w)
        : "r"(a[0]), "r"(a[1]), "r"(a[2]), "r"(a[3]), "r"(b0), "r"(b1));
}
__device__ __forceinline__ void cpa16(void* smem_dst, const void* gsrc) {
    uint32_t s = (uint32_t)__cvta_generic_to_shared(smem_dst);
    asm volatile("cp.async.cg.shared.global [%0], [%1], 16;" :: "r"(s), "l"(gsrc));
}
__device__ __forceinline__ void cpa_wait() {
    asm volatile("cp.async.commit_group;\ncp.async.wait_group 0;" ::: "memory");
}

// ======================================================================
// Encode: angles -> statevector -> tf32-split packed rows
// ======================================================================
__global__ void __launch_bounds__(256) encode_kernel(
    const float* __restrict__ x, const float* __restrict__ w,
    const float* __restrict__ bias, int isK)
{
    __shared__ float sw[NQV * DDIM];
    __shared__ float sb[NQV];
    int tid = threadIdx.x;
    if (tid < NQV * DDIM) sw[tid] = w[tid];
    if (tid < NQV) sb[tid] = bias[tid];
    __syncthreads();

    int n  = blockIdx.x * blockDim.x + tid;     // bh*1024 + pos
    int bh = n >> 10, loc = n & 1023;
    int b = bh >> 3, h = bh & 7;
    const float* xr = x + (size_t)((b * 1024 + loc) * HHN + h) * DDIM;

    float th[NQV];
#pragma unroll
    for (int j = 0; j < NQV; j++) th[j] = sb[j];
#pragma unroll 4
    for (int d = 0; d < DDIM; d += 4) {
        float4 xv = *(const float4*)(xr + d);
#pragma unroll
        for (int j = 0; j < NQV; j++) {
            th[j] += xv.x * sw[j * DDIM + d]     + xv.y * sw[j * DDIM + d + 1]
                   + xv.z * sw[j * DDIM + d + 2] + xv.w * sw[j * DDIM + d + 3];
        }
    }
#pragma unroll
    for (int j = 0; j < NQV; j++) th[j] = tanhf(th[j]) * PI_F;
    float bt[3];
#pragma unroll
    for (int p = 0; p < 3; p++) bt[p] = th[p] * th[p + 1];

    float co[16], si[16];
#pragma unroll
    for (int d = 0; d < 16; d++) {
        float a = 0.f;
        a += ((d >> 3) & 1) ? -th[0] : th[0];
        a += ((d >> 2) & 1) ? -th[1] : th[1];
        a += ((d >> 1) & 1) ? -th[2] : th[2];
        a += ( d       & 1) ? -th[3] : th[3];
        a += (((d >> 3) ^ (d >> 2)) & 1) ? -bt[0] : bt[0];
        a += (((d >> 2) ^ (d >> 1)) & 1) ? -bt[1] : bt[1];
        a += (((d >> 1) ^  d      ) & 1) ? -bt[2] : bt[2];
        sincosf(-0.5f * a, &si[d], &co[d]);
    }
    float re[16], im[16];
#pragma unroll
    for (int d = 0; d < 16; d++) { re[d] = co[d]; im[d] = si[d]; }
#pragma unroll
    for (int hs = 1; hs < 16; hs <<= 1) {
#pragma unroll
        for (int i = 0; i < 16; i++) {
            if ((i & hs) == 0) {
                int j2 = i | hs;
                float ar = re[i], ai = im[i], br = re[j2], bi = im[j2];
                re[i] = ar + br;  im[i] = ai + bi;
                re[j2] = ar - br; im[j2] = ai - bi;
            }
        }
    }

    float rh[16], ih[16], rl[16], il[16];
#pragma unroll
    for (int d = 0; d < 16; d++) {
        float tr = re[d] * 0.0625f, ti = im[d] * 0.0625f;
        float vr = tr * co[d] - ti * si[d];
        float vi = tr * si[d] + ti * co[d];
        tsplit(vr, rh[d], rl[d]);
        tsplit(vi, ih[d], il[d]);
    }

    if (!isK) {
        float4* o = (float4*)(g_qA + (size_t)n * 128);
#pragma unroll
        for (int j = 0; j < 4; j++) {
            o[j]      = make_float4(rh[4*j], rh[4*j+1], rh[4*j+2], rh[4*j+3]);
            o[4 + j]  = make_float4(ih[4*j], ih[4*j+1], ih[4*j+2], ih[4*j+3]);
            o[8 + j]  = make_float4(rl[4*j], rl[4*j+1], rl[4*j+2], rl[4*j+3]);
            o[12 + j] = make_float4(il[4*j], il[4*j+1], il[4*j+2], il[4*j+3]);
            o[16 + j] = make_float4(ih[4*j], ih[4*j+1], ih[4*j+2], ih[4*j+3]);
            o[20 + j] = make_float4(-rh[4*j], -rh[4*j+1], -rh[4*j+2], -rh[4*j+3]);
            o[24 + j] = make_float4(il[4*j], il[4*j+1], il[4*j+2], il[4*j+3]);
            o[28 + j] = make_float4(-rl[4*j], -rl[4*j+1], -rl[4*j+2], -rl[4*j+3]);
        }
    } else {
        float4* o = (float4*)(g_kB + (size_t)n * 64);
#pragma unroll
        for (int j = 0; j < 4; j++) {
            o[j]      = make_float4(rh[4*j], rh[4*j+1], rh[4*j+2], rh[4*j+3]);
            o[4 + j]  = make_float4(ih[4*j], ih[4*j+1], ih[4*j+2], ih[4*j+3]);
            o[8 + j]  = make_float4(rl[4*j], rl[4*j+1], rl[4*j+2], rl[4*j+3]);
            o[12 + j] = make_float4(il[4*j], il[4*j+1], il[4*j+2], il[4*j+3]);
        }
    }
}

// ======================================================================
// V split prep
// ======================================================================
__global__ void __launch_bounds__(256) vsplit_kernel(const float* __restrict__ v)
{
    int n = blockIdx.x * blockDim.x + threadIdx.x;   // bh*1024 + s
    int bh = n >> 10, s = n & 1023;
    int b = bh >> 3, h = bh & 7;
    const float* src = v + (size_t)((b * 1024 + s) * HHN + h) * DDIM;
    float* dst = g_vS + (size_t)n * 128;
#pragma unroll 8
    for (int d = 0; d < 64; d++) {
        float hi, lo; tsplit(src[d], hi, lo);
        dst[d] = hi; dst[64 + d] = lo;
    }
}

// ======================================================================
// Kernel S: raw scores (tensor, 3xTF32) + rowsums
// block = (bh, 64-l tile); warp = one m16 tile (16 rows = 8 l x {a,b})
// ======================================================================
#define SK_SMEM (256 * 68 * 4)
__global__ void __launch_bounds__(256, 3) attn_scores(float* __restrict__ out)
{
    extern __shared__ float ks[];     // [256][68]  K chunk [hi32|lo32]
    const int bh = blockIdx.y, l0 = blockIdx.x * 64;
    const int tid = threadIdx.x, w = tid >> 5, lane = tid & 31;
    const int gr = lane >> 2, ctg = lane & 3;

    // A fragments (resident): rows l0*2 + w*16 + {gr, gr+8}
    const float* qa = g_qA + (size_t)bh * 131072 + (size_t)(l0 * 2 + w * 16) * 64;
    uint32_t ah[4][4], al[4][4];
#pragma unroll
    for (int kk = 0; kk < 4; kk++) {
        int c0 = kk * 8 + ctg;
        ah[kk][0] = __float_as_uint(qa[gr * 64 + c0]);
        ah[kk][1] = __float_as_uint(qa[(gr + 8) * 64 + c0]);
        ah[kk][2] = __float_as_uint(qa[gr * 64 + c0 + 4]);
        ah[kk][3] = __float_as_uint(qa[(gr + 8) * 64 + c0 + 4]);
        al[kk][0] = __float_as_uint(qa[gr * 64 + 32 + c0]);
        al[kk][1] = __float_as_uint(qa[(gr + 8) * 64 + 32 + c0]);
        al[kk][2] = __float_as_uint(qa[gr * 64 + 32 + c0 + 4]);
        al[kk][3] = __float_as_uint(qa[(gr + 8) * 64 + 32 + c0 + 4]);
    }

    const float4* kg = (const float4*)(g_kB + (size_t)bh * 65536);
    float* wout = out + (size_t)CTX_ELEMS + (size_t)(bh * 1024 + l0) * 1024;
    const bool evengr = !(gr & 1);
    const int lt = w * 8 + (gr >> 1);
    const int lb = lt + 4;
    float rs0 = 0.f, rs1 = 0.f;

    for (int ch = 0; ch < 4; ch++) {
        __syncthreads();
#pragma unroll
        for (int j = 0; j < 16; j++) {
            int i = tid + j * 256;
            int s = i >> 4, q4 = i & 15;
            cpa16(&ks[s * 68 + q4 * 4], kg + (size_t)(ch * 256 + s) * 16 + q4);
        }
        cpa_wait();
        __syncthreads();

#pragma unroll 2
        for (int nt = 0; nt < 32; nt++) {
            int n0 = nt * 8;
            float4 c = make_float4(0.f, 0.f, 0.f, 0.f);
            const float* bc = &ks[(n0 + gr) * 68];
#pragma unroll
            for (int kk = 0; kk < 4; kk++) {
                int r0 = kk * 8 + ctg;
                uint32_t b0 = __float_as_uint(bc[r0]);
                uint32_t b1 = __float_as_uint(bc[r0 + 4]);
                uint32_t q0 = __float_as_uint(bc[32 + r0]);
                uint32_t q1 = __float_as_uint(bc[32 + r0 + 4]);
                mma_tf32(c, ah[kk], b0, b1);
                mma_tf32(c, ah[kk], q0, q1);
                mma_tf32(c, al[kk], b0, b1);
            }
            float p0 = c.x * c.x, p1 = c.y * c.y, p2 = c.z * c.z, p3 = c.w * c.w;
            p0 += __shfl_xor_sync(0xFFFFFFFFu, p0, 4);
            p1 += __shfl_xor_sync(0xFFFFFFFFu, p1, 4);
            p2 += __shfl_xor_sync(0xFFFFFFFFu, p2, 4);
            p3 += __shfl_xor_sync(0xFFFFFFFFu, p3, 4);
            if (evengr) {
                rs0 += p0 + p1; rs1 += p2 + p3;
                int col = ch * 256 + n0 + 2 * ctg;
                *(float2*)&wout[(size_t)lt * 1024 + col] = make_float2(p0, p1);
                *(float2*)&wout[(size_t)lb * 1024 + col] = make_float2(p2, p3);
            }
        }
    }
    rs0 += __shfl_xor_sync(0xFFFFFFFFu, rs0, 1);
    rs0 += __shfl_xor_sync(0xFFFFFFFFu, rs0, 2);
    rs1 += __shfl_xor_sync(0xFFFFFFFFu, rs1, 1);
    rs1 += __shfl_xor_sync(0xFFFFFFFFu, rs1, 2);
    if (evengr && ctg == 0) {
        g_rsum[bh * 1024 + l0 + lt] = rs0;
        g_rsum[bh * 1024 + l0 + lb] = rs1;
    }
}

// ======================================================================
// Kernel C: normalize weights (in place) + context = (raw @ Vsplit) * inv
// block = (bh, 64-l tile); warps = (mtile 0..3) x (nhalf 0..1)
// ======================================================================
#define SC_W (64 * 132)
#define SC_V (128 * 136)
#define CC_SMEM ((SC_W + SC_V) * 4)
__global__ void __launch_bounds__(256, 2) attn_context(float* __restrict__ out)
{
    extern __shared__ float sm[];
    float* wsm = sm;            // [64][132] raw weight chunk
    float* vsm = sm + SC_W;     // [128][136] V chunk [hi 0..63 | lo 68..131]
    __shared__ float sinv[64];

    const int bh = blockIdx.y, l0 = blockIdx.x * 64;
    const int b = bh >> 3, h = bh & 7;
    const int tid = threadIdx.x, w = tid >> 5, lane = tid & 31;
    const int gr = lane >> 2, ctg = lane & 3;
    const int mt = w & 3, nh = w >> 2;

    if (tid < 64) sinv[tid] = 1.0f / (g_rsum[bh * 1024 + l0 + tid] + 1e-6f);

    float* wraw = out + (size_t)CTX_ELEMS + (size_t)(bh * 1024 + l0) * 1024;
    const float4* vg = (const float4*)(g_vS + (size_t)bh * 131072);

    float4 cacc[4];
#pragma unroll
    for (int nt = 0; nt < 4; nt++) cacc[nt] = make_float4(0.f, 0.f, 0.f, 0.f);

    for (int ch = 0; ch < 8; ch++) {
        __syncthreads();
#pragma unroll
        for (int j = 0; j < 8; j++) {       // W raw chunk: 64 x 128
            int i = tid + j * 256;
            int l = i >> 5, f4 = i & 31;
            cpa16(&wsm[l * 132 + f4 * 4],
                  (const float4*)wraw + (size_t)l * 256 + ch * 32 + f4);
        }
#pragma unroll
        for (int j = 0; j < 16; j++) {      // V chunk: 128 x [hi64|lo64]
            int i = tid + j * 256;
            int s = i >> 5, f4 = i & 31;
            int dst = s * 136 + (f4 < 16 ? f4 * 4 : 68 + (f4 - 16) * 4);
            cpa16(&vsm[dst], vg + (size_t)(ch * 128 + s) * 32 + f4);
        }
        cpa_wait();
        __syncthreads();

        // normalized weights write-back
#pragma unroll
        for (int j = 0; j < 8; j++) {
            int i = tid + j * 256;
            int l = i >> 5, f4 = i & 31;
            float4 v = *(float4*)&wsm[l * 132 + f4 * 4];
            float iv = sinv[l];
            v.x *= iv; v.y *= iv; v.z *= iv; v.w *= iv;
            ((float4*)wraw)[(size_t)l * 256 + ch * 32 + f4] = v;
        }

#pragma unroll 1
        for (int kk = 0; kk < 16; kk++) {
            int k0 = kk * 8;
            float hi, lo;
            uint32_t ahh[4], all[4];
            float w00 = wsm[(mt * 16 + gr) * 132 + k0 + ctg];
            float w10 = wsm[(mt * 16 + gr + 8) * 132 + k0 + ctg];
            float w01 = wsm[(mt * 16 + gr) * 132 + k0 + ctg + 4];
            float w11 = wsm[(mt * 16 + gr + 8) * 132 + k0 + ctg + 4];
            tsplit(w00, hi, lo); ahh[0] = __float_as_uint(hi); all[0] = __float_as_uint(lo);
            tsplit(w10, hi, lo); ahh[1] = __float_as_uint(hi); all[1] = __float_as_uint(lo);
            tsplit(w01, hi, lo); ahh[2] = __float_as_uint(hi); all[2] = __float_as_uint(lo);
            tsplit(w11, hi, lo); ahh[3] = __float_as_uint(hi); all[3] = __float_as_uint(lo);
            const float* vr0 = &vsm[(k0 + ctg) * 136];
            const float* vr1 = &vsm[(k0 + ctg + 4) * 136];
#pragma unroll
            for (int nt = 0; nt < 4; nt++) {
                int d0 = nh * 32 + nt * 8 + gr;
                uint32_t b0 = __float_as_uint(vr0[d0]);
                uint32_t b1 = __float_as_uint(vr1[d0]);
                uint32_t q0 = __float_as_uint(vr0[68 + d0]);
                uint32_t q1 = __float_as_uint(vr1[68 + d0]);
                mma_tf32(cacc[nt], ahh, b0, b1);
                mma_tf32(cacc[nt], all, b0, b1);
                mma_tf32(cacc[nt], ahh, q0, q1);
            }
        }
    }

    float ivt = sinv[mt * 16 + gr], ivb = sinv[mt * 16 + gr + 8];
    int lt = l0 + mt * 16 + gr, lb = lt + 8;
#pragma unroll
    for (int nt = 0; nt < 4; nt++) {
        int d = nh * 32 + nt * 8 + 2 * ctg;
        *(float2*)&out[((size_t)(b * 1024 + lt) * 8 + h) * 64 + d]
            = make_float2(cacc[nt].x * ivt, cacc[nt].y * ivt);
        *(float2*)&out[((size_t)(b * 1024 + lb) * 8 + h) * 64 + d]
            = make_float2(cacc[nt].z * ivb, cacc[nt].w * ivb);
    }
}

// ======================================================================
extern "C" void kernel_launch(void* const* d_in, const int* in_sizes, int n_in,
                              void* d_out, int out_size)
{
    (void)in_sizes; (void)n_in; (void)out_size;
    const float* q  = (const float*)d_in[0];
    const float* k  = (const float*)d_in[1];
    const float* v  = (const float*)d_in[2];
    const float* wq = (const float*)d_in[3];
    const float* bq = (const float*)d_in[4];
    const float* wk = (const float*)d_in[5];
    const float* bk = (const float*)d_in[6];
    float* out = (float*)d_out;

    cudaFuncSetAttribute(attn_scores,  cudaFuncAttributeMaxDynamicSharedMemorySize, SK_SMEM);
    cudaFuncSetAttribute(attn_context, cudaFuncAttributeMaxDynamicSharedMemorySize, CC_SMEM);

    encode_kernel<<<256, 256>>>(q, wq, bq, 0);
    encode_kernel<<<256, 256>>>(k, wk, bk, 1);
    vsplit_kernel<<<256, 256>>>(v);
    attn_scores<<<dim3(16, BHN), 256, SK_SMEM>>>(out);
    attn_context<<<dim3(16, BHN), 256, CC_SMEM>>>(out);
}